// round 10
// baseline (speedup 1.0000x reference)
#include <cuda_runtime.h>
#include <cuda_bf16.h>
#include <cuda_fp16.h>
#include <mma.h>

using namespace nvcuda;

#define NN 100000
#define EE 1600000
#define DD 128

// d_g padded by 128 rows so the last GEMM block's full-tile stores stay in-bounds.
__device__ float  d_g [(size_t)(NN + 128) * DD];
__device__ __half d_gh[(size_t)(NN + 128) * DD];   // fp16 copy for scatter reads
__device__ float  d_dinv[NN];
__device__ int    d_deg[NN];
__device__ float  d_WcT[DD * DD];   // WcT[k][c] = Wc[c][k], tf32-rounded

// ---------------------------------------------------------------------------
// 1) deg = 1 (self loop)
__global__ void prep_kernel(int n) {
    int i = blockIdx.x * blockDim.x + threadIdx.x;
    if (i < n) d_deg[i] = 1;
}

// 2) count in-degrees over edge targets; 4 edges per thread
__global__ void count_deg_kernel(const int* __restrict__ ei, int E) {
    int t = blockIdx.x * blockDim.x + threadIdx.x;
    int e = t * 4;
    if (e + 4 <= E) {
        int4 c = __ldg((const int4*)&ei[E + e]);
        atomicAdd(&d_deg[c.x], 1);
        atomicAdd(&d_deg[c.y], 1);
        atomicAdd(&d_deg[c.z], 1);
        atomicAdd(&d_deg[c.w], 1);
    } else {
        for (; e < E; e++) atomicAdd(&d_deg[__ldg(&ei[E + e])], 1);
    }
}

// 3) fused: dinv = rsqrt(deg)  +  WcT[k][c] = sum_m Wg[c][m]*Wl[m][k] (tf32)
__global__ void dinv_combine_kernel(const float* __restrict__ Wl,
                                    const float* __restrict__ Wg, int n) {
    if (blockIdx.x < DD) {
        int k = blockIdx.x;
        int c = threadIdx.x;
        float s0 = 0.f, s1 = 0.f, s2 = 0.f, s3 = 0.f;
#pragma unroll 8
        for (int m = 0; m < DD; m += 4) {
            s0 += __ldg(&Wg[c * DD + m + 0]) * __ldg(&Wl[(m + 0) * DD + k]);
            s1 += __ldg(&Wg[c * DD + m + 1]) * __ldg(&Wl[(m + 1) * DD + k]);
            s2 += __ldg(&Wg[c * DD + m + 2]) * __ldg(&Wl[(m + 2) * DD + k]);
            s3 += __ldg(&Wg[c * DD + m + 3]) * __ldg(&Wl[(m + 3) * DD + k]);
        }
        d_WcT[k * DD + c] = wmma::__float_to_tf32((s0 + s1) + (s2 + s3));
    } else {
        int i = (blockIdx.x - DD) * blockDim.x + threadIdx.x;
        if (i < n) d_dinv[i] = rsqrtf((float)d_deg[i]);
    }
}

// 4) GEMM + fused epilogue.
//    g[i][:]   = (dinv[i] * x[i]) @ WcT      (fp32 d_g + fp16 d_gh)
//    out[i][:] = dinv[i] * g[i] + b          (self-loop + bias init)
__global__ __launch_bounds__(256, 2) void gemm_g_kernel(const float* __restrict__ x,
                                                        const float* __restrict__ bias,
                                                        float* __restrict__ out, int n) {
    __shared__ float xs[2][128][36];
    __shared__ float ws[2][32][132];

    const int tid = threadIdx.x;
    const int row0 = blockIdx.x * 128;
    const int warp = tid >> 5;
    const int wrow = (warp >> 1) * 32;
    const int wcol = (warp & 1) * 64;

    const int xr = tid >> 3;
    const int xf = tid & 7;
    float dinv_r[4];
#pragma unroll
    for (int p = 0; p < 4; p++) {
        int grow = row0 + xr + 32 * p;
        dinv_r[p] = (grow < n) ? d_dinv[grow] : 0.f;
    }

    const float4* x4 = (const float4*)x;
    const float4* w4 = (const float4*)d_WcT;

    wmma::fragment<wmma::accumulator, 16, 16, 8, float> acc[2][4];
#pragma unroll
    for (int i = 0; i < 2; i++)
#pragma unroll
        for (int j = 0; j < 4; j++) wmma::fill_fragment(acc[i][j], 0.0f);

    float4 xreg[4], wreg[4];

    auto ldg_chunk = [&](int kb) {
#pragma unroll
        for (int p = 0; p < 4; p++) {
            int grow = row0 + xr + 32 * p;
            xreg[p] = (grow < n) ? __ldg(&x4[grow * 32 + kb * 8 + xf])
                                 : make_float4(0.f, 0.f, 0.f, 0.f);
        }
#pragma unroll
        for (int q = 0; q < 4; q++) {
            int lin = tid * 4 + q;
            int kl = lin >> 5;
            int fc = lin & 31;
            wreg[q] = __ldg(&w4[(kb * 32 + kl) * 32 + fc]);
        }
    };
    auto sts_chunk = [&](int buf) {
#pragma unroll
        for (int p = 0; p < 4; p++) {
            float di = dinv_r[p];
            float4 o;
            o.x = wmma::__float_to_tf32(xreg[p].x * di);
            o.y = wmma::__float_to_tf32(xreg[p].y * di);
            o.z = wmma::__float_to_tf32(xreg[p].z * di);
            o.w = wmma::__float_to_tf32(xreg[p].w * di);
            *(float4*)&xs[buf][xr + 32 * p][xf * 4] = o;
        }
#pragma unroll
        for (int q = 0; q < 4; q++) {
            int lin = tid * 4 + q;
            int kl = lin >> 5;
            int fc = lin & 31;
            *(float4*)&ws[buf][kl][fc * 4] = wreg[q];
        }
    };

    ldg_chunk(0);
    sts_chunk(0);
    __syncthreads();

    for (int kb = 0; kb < 4; kb++) {
        int buf = kb & 1;
        if (kb < 3) ldg_chunk(kb + 1);

#pragma unroll
        for (int ks = 0; ks < 4; ks++) {
            wmma::fragment<wmma::matrix_a, 16, 16, 8, wmma::precision::tf32, wmma::row_major> a[2];
            wmma::load_matrix_sync(a[0], &xs[buf][wrow][ks * 8], 36);
            wmma::load_matrix_sync(a[1], &xs[buf][wrow + 16][ks * 8], 36);
#pragma unroll
            for (int j = 0; j < 4; j++) {
                wmma::fragment<wmma::matrix_b, 16, 16, 8, wmma::precision::tf32, wmma::row_major> b;
                wmma::load_matrix_sync(b, &ws[buf][ks * 8][wcol + j * 16], 132);
                wmma::mma_sync(acc[0][j], a[0], b, acc[0][j]);
                wmma::mma_sync(acc[1][j], a[1], b, acc[1][j]);
            }
        }

        if (kb < 3) {
            sts_chunk(buf ^ 1);
            __syncthreads();
        }
    }

    // store g (fp32)
#pragma unroll
    for (int i = 0; i < 2; i++)
#pragma unroll
        for (int j = 0; j < 4; j++) {
            wmma::store_matrix_sync(
                &d_g[(size_t)(row0 + wrow + i * 16) * DD + wcol + j * 16],
                acc[i][j], DD, wmma::mem_row_major);
        }
    __syncthreads();

    // fused epilogue: out = dinv[r]*g + b; d_gh = fp16(g)   (L2-hit read-back)
    const float4* g4 = (const float4*)d_g;
    float4* o4 = (float4*)out;
    uint2* gh2 = (uint2*)d_gh;
#pragma unroll
    for (int i = 0; i < 16; i++) {
        int idx = tid + 256 * i;
        int r = row0 + (idx >> 5);
        if (r < n) {
            int c4 = idx & 31;
            float di = d_dinv[r];
            float4 g = g4[r * 32 + c4];
            float4 bb = __ldg(&((const float4*)bias)[c4]);
            float4 o;
            o.x = di * g.x + bb.x;
            o.y = di * g.y + bb.y;
            o.z = di * g.z + bb.z;
            o.w = di * g.w + bb.w;
            o4[r * 32 + c4] = o;
            __half2 h0 = __float22half2_rn(make_float2(g.x, g.y));
            __half2 h1 = __float22half2_rn(make_float2(g.z, g.w));
            uint2 packed;
            packed.x = *reinterpret_cast<unsigned*>(&h0);
            packed.y = *reinterpret_cast<unsigned*>(&h1);
            gh2[r * 32 + c4] = packed;
        }
    }
}

// 5) scatter: fp16 message reads (256B/row), fp32 v4 atomic accumulation
#define EPW 8
__global__ void scatter_kernel(const int* __restrict__ ei,
                               float* __restrict__ out, int E) {
    int warp = (blockIdx.x * blockDim.x + threadIdx.x) >> 5;
    int lane = threadIdx.x & 31;
    const uint2* gh2 = (const uint2*)d_gh;
    float4* o4 = (float4*)out;
    int base = warp * EPW;

    auto do_edge = [&](int e) {
        int r = __ldg(&ei[e]);
        int c = __ldg(&ei[E + e]);
        float dc = __ldg(&d_dinv[c]);
        uint2 raw = __ldg(&gh2[r * 32 + lane]);
        __half2 h0 = *reinterpret_cast<__half2*>(&raw.x);
        __half2 h1 = *reinterpret_cast<__half2*>(&raw.y);
        float2 f0 = __half22float2(h0);
        float2 f1 = __half22float2(h1);
        float4 v;
        v.x = f0.x * dc; v.y = f0.y * dc; v.z = f1.x * dc; v.w = f1.y * dc;
        float4* addr = &o4[c * 32 + lane];
        asm volatile("red.global.add.v4.f32 [%0], {%1,%2,%3,%4};"
                     :: "l"(addr), "f"(v.x), "f"(v.y), "f"(v.z), "f"(v.w)
                     : "memory");
    };

    if (base + EPW <= E) {
#pragma unroll
        for (int t = 0; t < EPW; t++) do_edge(base + t);
    } else {
        for (int e = base; e < E; e++) do_edge(e);
    }
}

extern "C" void kernel_launch(void* const* d_in, const int* in_sizes, int n_in,
                              void* d_out, int out_size) {
    const float* x  = (const float*)d_in[0];
    const int*   ei = (const int*)d_in[1];     // int32 on device
    const float* Wl = (const float*)d_in[2];
    const float* Wg = (const float*)d_in[3];
    const float* b  = (const float*)d_in[4];
    float* out = (float*)d_out;

    int n = in_sizes[0] / DD;     // 100000
    int E = in_sizes[1] / 2;      // 1600000

    prep_kernel<<<(n + 255) / 256, 256>>>(n);
    int qthreads = (E + 3) / 4;
    count_deg_kernel<<<(qthreads + 255) / 256, 256>>>(ei, E);
    dinv_combine_kernel<<<DD + (n + 127) / 128, 128>>>(Wl, Wg, n);
    gemm_g_kernel<<<(n + 127) / 128, 256>>>(x, b, out, n);

    int warps = (E + EPW - 1) / EPW;
    int sblocks = (warps * 32 + 255) / 256;
    scatter_kernel<<<sblocks, 256>>>(ei, out, E);
}

// round 12
// speedup vs baseline: 1.1930x; 1.1930x over previous
#include <cuda_runtime.h>
#include <cuda_fp16.h>
#include <mma.h>
#include <cstdint>

using namespace nvcuda;

#define NN 100000
#define EE 1600000
#define DD 128

// Scratch (__device__ globals per allocation rules). d_g padded 128 rows.
__device__ float  d_g[(size_t)(NN + 128) * DD];
__device__ float  d_dinv[NN];
__device__ int    d_deg[NN];
__device__ __half d_WcTh[DD * DD];   // WcT[k][c] = Wc[c][k], fp16

// ---------------------------------------------------------------------------
// 1) deg = 1 (self loop)
__global__ void prep_kernel(int n) {
    int i = blockIdx.x * blockDim.x + threadIdx.x;
    if (i < n) d_deg[i] = 1;
}

// 2) count in-degrees; 4 edges per thread
__global__ void count_deg_kernel(const int* __restrict__ ei, int E) {
    int t = blockIdx.x * blockDim.x + threadIdx.x;
    int e = t * 4;
    if (e + 4 <= E) {
        int4 c = __ldg((const int4*)&ei[E + e]);
        atomicAdd(&d_deg[c.x], 1);
        atomicAdd(&d_deg[c.y], 1);
        atomicAdd(&d_deg[c.z], 1);
        atomicAdd(&d_deg[c.w], 1);
    } else {
        for (; e < E; e++) atomicAdd(&d_deg[__ldg(&ei[E + e])], 1);
    }
}

// 3) fused: dinv = rsqrt(deg)  +  WcTh[k][c] = fp16(sum_m Wg[c][m]*Wl[m][k])
__global__ void dinv_combine_kernel(const float* __restrict__ Wl,
                                    const float* __restrict__ Wg, int n) {
    if (blockIdx.x < DD) {
        int k = blockIdx.x;
        int c = threadIdx.x;
        float s0 = 0.f, s1 = 0.f, s2 = 0.f, s3 = 0.f;
#pragma unroll 8
        for (int m = 0; m < DD; m += 4) {
            s0 += __ldg(&Wg[c * DD + m + 0]) * __ldg(&Wl[(m + 0) * DD + k]);
            s1 += __ldg(&Wg[c * DD + m + 1]) * __ldg(&Wl[(m + 1) * DD + k]);
            s2 += __ldg(&Wg[c * DD + m + 2]) * __ldg(&Wl[(m + 2) * DD + k]);
            s3 += __ldg(&Wg[c * DD + m + 3]) * __ldg(&Wl[(m + 3) * DD + k]);
        }
        d_WcTh[k * DD + c] = __float2half_rn((s0 + s1) + (s2 + s3));
    } else {
        int i = (blockIdx.x - DD) * blockDim.x + threadIdx.x;
        if (i < n) d_dinv[i] = rsqrtf((float)d_deg[i]);
    }
}

// 4) fp16 wmma GEMM + fused epilogue.
//    g[i][:]   = (dinv[i] * x[i]) @ WcT    (fp16 inputs, fp32 accum)
//    out[i][:] = dinv[i] * g[i] + b
//    Block: 128 rows x 128 cols, 8 warps, warp tile 32x64.
//    Whole K=128 staged once in smem (A 32KB + B 32KB + pad).
#define XS_LD 136   // halves; 272B row stride, 16B aligned, pad kills conflicts
#define SMEM_HALVES (2 * 128 * XS_LD)

__global__ __launch_bounds__(256, 2) void gemm_g_kernel(const float* __restrict__ x,
                                                        const float* __restrict__ bias,
                                                        float* __restrict__ out, int n) {
    extern __shared__ __half sm[];
    __half* xs = sm;                    // [128][XS_LD] : A = fp16(dinv*x)
    __half* ws = sm + 128 * XS_LD;      // [128][XS_LD] : B = WcT (k x c)

    const int tid = threadIdx.x;
    const int row0 = blockIdx.x * 128;
    const int warp = tid >> 5;
    const int wrow = (warp >> 1) * 32;   // 0,32,64,96
    const int wcol = (warp & 1) * 64;    // 0,64

    // Load A: 128 rows x 32 float4; convert to half with dinv. 16 float4/thread.
    const float4* x4 = (const float4*)x;
#pragma unroll
    for (int i = 0; i < 16; i++) {
        int idx = tid + 256 * i;        // 0..4095
        int r = idx >> 5;
        int c4 = idx & 31;
        int grow = row0 + r;
        float4 v = make_float4(0.f, 0.f, 0.f, 0.f);
        float di = 0.f;
        if (grow < n) {
            di = d_dinv[grow];
            v = __ldg(&x4[grow * 32 + c4]);
        }
        __half2 h0 = __floats2half2_rn(v.x * di, v.y * di);
        __half2 h1 = __floats2half2_rn(v.z * di, v.w * di);
        uint2 p;
        p.x = *reinterpret_cast<unsigned*>(&h0);
        p.y = *reinterpret_cast<unsigned*>(&h1);
        *(uint2*)&xs[r * XS_LD + c4 * 4] = p;
    }
    // Load B: WcTh is 128x128 half row-major = 128 rows x 16 uint4. 8/thread.
    const uint4* w16 = (const uint4*)d_WcTh;
#pragma unroll
    for (int i = 0; i < 8; i++) {
        int idx = tid + 256 * i;        // 0..2047
        int k = idx >> 4;
        int c8 = idx & 15;              // uint4 = 8 halves
        uint4 v = __ldg(&w16[k * 16 + c8]);
        *(uint4*)&ws[k * XS_LD + c8 * 8] = v;
    }
    __syncthreads();

    wmma::fragment<wmma::accumulator, 16, 16, 16, float> acc[2][4];
#pragma unroll
    for (int i = 0; i < 2; i++)
#pragma unroll
        for (int j = 0; j < 4; j++) wmma::fill_fragment(acc[i][j], 0.0f);

#pragma unroll
    for (int ks = 0; ks < 8; ks++) {
        wmma::fragment<wmma::matrix_a, 16, 16, 16, __half, wmma::row_major> a[2];
        wmma::load_matrix_sync(a[0], &xs[wrow * XS_LD + ks * 16], XS_LD);
        wmma::load_matrix_sync(a[1], &xs[(wrow + 16) * XS_LD + ks * 16], XS_LD);
#pragma unroll
        for (int j = 0; j < 4; j++) {
            wmma::fragment<wmma::matrix_b, 16, 16, 16, __half, wmma::row_major> b;
            wmma::load_matrix_sync(b, &ws[(ks * 16) * XS_LD + wcol + j * 16], XS_LD);
            wmma::mma_sync(acc[0][j], a[0], b, acc[0][j]);
            wmma::mma_sync(acc[1][j], a[1], b, acc[1][j]);
        }
    }

    // store g (fp32)
#pragma unroll
    for (int i = 0; i < 2; i++)
#pragma unroll
        for (int j = 0; j < 4; j++) {
            wmma::store_matrix_sync(
                &d_g[(size_t)(row0 + wrow + i * 16) * DD + wcol + j * 16],
                acc[i][j], DD, wmma::mem_row_major);
        }
    __syncthreads();   // block's d_g rows complete

    // fused epilogue: out = dinv[r]*g + b  (L2-hit read-back of d_g)
    const float4* g4 = (const float4*)d_g;
    const float4* bias4 = (const float4*)bias;
    float4* o4 = (float4*)out;
#pragma unroll
    for (int i = 0; i < 16; i++) {
        int idx = tid + 256 * i;
        int r = row0 + (idx >> 5);
        if (r < n) {
            int c4 = idx & 31;
            float di = d_dinv[r];
            float4 g = g4[r * 32 + c4];
            float4 bb = __ldg(&bias4[c4]);
            float4 o;
            o.x = di * g.x + bb.x;
            o.y = di * g.y + bb.y;
            o.z = di * g.z + bb.z;
            o.w = di * g.w + bb.w;
            o4[r * 32 + c4] = o;
        }
    }
}

// 5) scatter: EPW edges per warp; msg = dinv[c] * g[r]; fp32 v4 atomic adds
#define EPW 8
__global__ void scatter_kernel(const int* __restrict__ ei,
                               float* __restrict__ out, int E) {
    int warp = (blockIdx.x * blockDim.x + threadIdx.x) >> 5;
    int lane = threadIdx.x & 31;
    const float4* g4 = (const float4*)d_g;
    float4* o4 = (float4*)out;
    int base = warp * EPW;

    auto do_edge = [&](int e) {
        int r = __ldg(&ei[e]);
        int c = __ldg(&ei[E + e]);
        float dc = __ldg(&d_dinv[c]);
        float4 v = __ldg(&g4[r * 32 + lane]);
        v.x *= dc; v.y *= dc; v.z *= dc; v.w *= dc;
        float4* addr = &o4[c * 32 + lane];
        asm volatile("red.global.add.v4.f32 [%0], {%1,%2,%3,%4};"
                     :: "l"(addr), "f"(v.x), "f"(v.y), "f"(v.z), "f"(v.w)
                     : "memory");
    };

    if (base + EPW <= E) {
#pragma unroll
        for (int t = 0; t < EPW; t++) do_edge(base + t);
    } else {
        for (int e = base; e < E; e++) do_edge(e);
    }
}

extern "C" void kernel_launch(void* const* d_in, const int* in_sizes, int n_in,
                              void* d_out, int out_size) {
    const float* x  = (const float*)d_in[0];
    const int*   ei = (const int*)d_in[1];     // int32 on device
    const float* Wl = (const float*)d_in[2];
    const float* Wg = (const float*)d_in[3];
    const float* b  = (const float*)d_in[4];
    float* out = (float*)d_out;

    int n = in_sizes[0] / DD;     // 100000
    int E = in_sizes[1] / 2;      // 1600000

    prep_kernel<<<(n + 255) / 256, 256>>>(n);
    int qthreads = (E + 3) / 4;
    count_deg_kernel<<<(qthreads + 255) / 256, 256>>>(ei, E);
    dinv_combine_kernel<<<DD + (n + 127) / 128, 128>>>(Wl, Wg, n);

    size_t smem_bytes = SMEM_HALVES * sizeof(__half);   // 69632
    cudaFuncSetAttribute(gemm_g_kernel, cudaFuncAttributeMaxDynamicSharedMemorySize,
                         (int)smem_bytes);
    gemm_g_kernel<<<(n + 127) / 128, 256, smem_bytes>>>(x, b, out, n);

    int warps = (E + EPW - 1) / EPW;
    int sblocks = (warps * 32 + 255) / 256;
    scatter_kernel<<<sblocks, 256>>>(ei, out, E);
}